// round 1
// baseline (speedup 1.0000x reference)
#include <cuda_runtime.h>
#include <math.h>

#define NN 100000
#define EE 1000000

// ---------------- device scratch (no allocation allowed) ----------------
__device__ int    d_cnt[NN];
__device__ int    d_off[NN + 1];
__device__ int    d_cur[NN];
__device__ int    d_bsum[128];
__device__ int    d_eid[EE];
__device__ int    d_ssrc[EE];
__device__ float  d_hagg0[(size_t)NN * 64];
__device__ float  d_efagg[(size_t)NN * 64];
__device__ float  d_hagg [(size_t)NN * 64];
__device__ float  d_h1   [(size_t)NN * 64];
__device__ float  d_Wc[2][192 * 64];
__device__ float  d_cv[2][64];
__device__ double d_loss;

// ---------------- init ----------------
__global__ void k_init(int n) {
    int i = blockIdx.x * blockDim.x + threadIdx.x;
    if (i < n) { d_cnt[i] = 0; d_cur[i] = 0; }
    if (i == 0) d_loss = 0.0;
}

__global__ void k_hist(const int* __restrict__ dst, int E) {
    int e = blockIdx.x * blockDim.x + threadIdx.x;
    if (e < E) atomicAdd(&d_cnt[dst[e]], 1);
}

// ---------------- 3-phase exclusive scan over counts -> d_off ----------------
__global__ void k_scan_a(int n) {
    __shared__ int ws[32];
    int i = blockIdx.x * 1024 + threadIdx.x;
    int lane = threadIdx.x & 31, wid = threadIdx.x >> 5;
    int v = (i < n) ? d_cnt[i] : 0;
    int x = v;
    #pragma unroll
    for (int o = 1; o < 32; o <<= 1) { int y = __shfl_up_sync(~0u, x, o); if (lane >= o) x += y; }
    if (lane == 31) ws[wid] = x;
    __syncthreads();
    if (wid == 0) {
        int w = ws[lane];
        #pragma unroll
        for (int o = 1; o < 32; o <<= 1) { int y = __shfl_up_sync(~0u, w, o); if (lane >= o) w += y; }
        ws[lane] = w;
    }
    __syncthreads();
    int incl = x + (wid > 0 ? ws[wid - 1] : 0);
    if (i < n) d_off[i] = incl - v;                 // block-local exclusive
    if (threadIdx.x == 1023) d_bsum[blockIdx.x] = incl;
}

__global__ void k_scan_b(int nb, int Etot, int n) {
    __shared__ int s[128];
    int t = threadIdx.x;
    int orig = (t < nb) ? d_bsum[t] : 0;
    s[t] = orig;
    __syncthreads();
    for (int o = 1; o < 128; o <<= 1) {
        int add = (t >= o) ? s[t - o] : 0;
        __syncthreads();
        s[t] += add;
        __syncthreads();
    }
    if (t < nb) d_bsum[t] = s[t] - orig;            // exclusive block offsets
    if (t == 0) d_off[n] = Etot;
}

__global__ void k_scan_c(int n) {
    int i = blockIdx.x * blockDim.x + threadIdx.x;
    if (i < n) d_off[i] += d_bsum[i >> 10];
}

__global__ void k_scatter(const int* __restrict__ src, const int* __restrict__ dst, int E) {
    int e = blockIdx.x * blockDim.x + threadIdx.x;
    if (e < E) {
        int d = dst[e];
        int p = d_off[d] + atomicAdd(&d_cur[d], 1);
        d_eid[p]  = e;
        d_ssrc[p] = src[e];
    }
}

// ---------------- fold Wmsg into Wapply ----------------
// Wc[k][j]        = Wap[j][k]                                  (k in [0,64))
// Wc[64+k'][j]    = sum_t Wmsg[t][k'] * Wap[j][64+t]           (k' in [0,128), stacked)
// cv[j]           = sum_t bmsg[t]     * Wap[j][64+t]
__global__ void k_fold(const float* __restrict__ Wmsg, const float* __restrict__ bmsg,
                       const float* __restrict__ Wap, int layer) {
    __shared__ float Wn[64][64];   // Wn[t][j] = Wap[j][64+t]
    __shared__ float bm[64];
    int tid = threadIdx.x;
    for (int idx = tid; idx < 64 * 64; idx += 256) {
        int j = idx >> 6, t = idx & 63;
        Wn[t][j] = Wap[j * 128 + 64 + t];
    }
    if (tid < 64) bm[tid] = bmsg[tid];
    __syncthreads();
    for (int idx = tid; idx < 192 * 64; idx += 256) {
        int k = idx >> 6, j = idx & 63;
        float r;
        if (k < 64) {
            r = Wap[j * 128 + k];
        } else {
            int col = k - 64;   // spans both h-part (0..63) and ef-part (64..127) of Wmsg
            float a = 0.f;
            #pragma unroll
            for (int t = 0; t < 64; ++t) a += Wmsg[t * 128 + col] * Wn[t][j];
            r = a;
        }
        d_Wc[layer][k * 64 + j] = r;
    }
    for (int j = tid; j < 64; j += 256) {
        float a = 0.f;
        #pragma unroll
        for (int t = 0; t < 64; ++t) a += bm[t] * Wn[t][j];
        d_cv[layer][j] = a;
    }
}

// ---------------- CSR segment-mean aggregation (one warp per node) ----------------
// use_eid == 0 : rows indexed by d_ssrc  (h aggregation)
// use_eid == 1 : rows indexed by d_eid, optionally through perm (ef aggregation)
__global__ void k_agg(const float* __restrict__ feat, const int* __restrict__ perm,
                      int use_eid, float* __restrict__ out, int n) {
    int gw   = (blockIdx.x * blockDim.x + threadIdx.x) >> 5;
    int lane = threadIdx.x & 31;
    if (gw >= n) return;
    int beg = d_off[gw], end = d_off[gw + 1];
    float ax = 0.f, ay = 0.f;
    for (int k = beg; k < end; ++k) {
        int row;
        if (use_eid) {
            int e = __ldg(&d_eid[k]);
            row = perm ? __ldg(&perm[e]) : e;
        } else {
            row = __ldg(&d_ssrc[k]);
        }
        float2 v = *reinterpret_cast<const float2*>(feat + (size_t)row * 64 + lane * 2);
        ax += v.x; ay += v.y;
    }
    float inv = 1.f / fmaxf((float)(end - beg), 1.f);  // pre-scale by 1/max(cnt,1)
    *reinterpret_cast<float2*>(out + (size_t)gw * 64 + lane * 2) = make_float2(ax * inv, ay * inv);
}

// ---------------- fused layer GEMM: out = relu([hin,haggs,efaggs] @ Wc + bap + ind*cv) ----------------
// mode 0: write out. mode 1: BCE target=1 (sum log1p(exp(-x))). mode 2: target=0 (sum x+log1p(exp(-x))).
__global__ void __launch_bounds__(256) k_layer(
    const float* __restrict__ hin, const float* __restrict__ haggs,
    const float* __restrict__ efaggs, int layer,
    const float* __restrict__ bap, float* __restrict__ out, int n, int mode)
{
    __shared__ float Xs[128][65];   // 128 nodes x 64 feats (pad 65: conflict-free)
    __shared__ float Ws[32][64];    // k-panel of 32 x 64 outputs
    __shared__ float wred[8];

    int tid  = threadIdx.x;
    int colg = tid & 15;            // 16 col groups x 4 cols
    int rowg = tid >> 4;            // 16 row groups x 8 rows
    int node0 = blockIdx.x * 128;

    float acc[8][4];
    #pragma unroll
    for (int i = 0; i < 8; ++i)
        #pragma unroll
        for (int c = 0; c < 4; ++c) acc[i][c] = 0.f;

    const float* Wc = d_Wc[layer];

    for (int p = 0; p < 3; ++p) {
        const float* S = (p == 0) ? hin : (p == 1) ? haggs : efaggs;
        __syncthreads();
        // load X tile [128][64] (coalesced: 16 threads per node row)
        #pragma unroll
        for (int it = 0; it < 8; ++it) {
            int t  = tid + it * 256;
            int r  = t >> 4;
            int c4 = (t & 15) << 2;
            int nd = node0 + r;
            float4 v = make_float4(0.f, 0.f, 0.f, 0.f);
            if (nd < n) v = *reinterpret_cast<const float4*>(S + (size_t)nd * 64 + c4);
            Xs[r][c4] = v.x; Xs[r][c4 + 1] = v.y; Xs[r][c4 + 2] = v.z; Xs[r][c4 + 3] = v.w;
        }
        for (int h = 0; h < 2; ++h) {
            if (h) __syncthreads();
            #pragma unroll
            for (int it = 0; it < 2; ++it) {
                int t = tid + it * 256;   // float4 index into Ws (512 total)
                reinterpret_cast<float4*>(&Ws[0][0])[t] =
                    *reinterpret_cast<const float4*>(Wc + (p * 64 + h * 32) * 64 + t * 4);
            }
            __syncthreads();
            #pragma unroll 4
            for (int k = 0; k < 32; ++k) {
                float4 wv = *reinterpret_cast<const float4*>(&Ws[k][colg << 2]);
                #pragma unroll
                for (int i = 0; i < 8; ++i) {
                    float x = Xs[rowg * 8 + i][h * 32 + k];
                    acc[i][0] += x * wv.x;
                    acc[i][1] += x * wv.y;
                    acc[i][2] += x * wv.z;
                    acc[i][3] += x * wv.w;
                }
            }
        }
    }

    // epilogue
    int j0 = colg << 2;
    float b0 = bap[j0], b1 = bap[j0 + 1], b2 = bap[j0 + 2], b3 = bap[j0 + 3];
    const float* cv = d_cv[layer];
    float c0 = cv[j0], c1 = cv[j0 + 1], c2 = cv[j0 + 2], c3 = cv[j0 + 3];

    if (mode == 0) {
        #pragma unroll
        for (int i = 0; i < 8; ++i) {
            int nd = node0 + rowg * 8 + i;
            if (nd < n) {
                float ind = (d_off[nd + 1] > d_off[nd]) ? 1.f : 0.f;
                float4 o;
                o.x = fmaxf(acc[i][0] + b0 + ind * c0, 0.f);
                o.y = fmaxf(acc[i][1] + b1 + ind * c1, 0.f);
                o.z = fmaxf(acc[i][2] + b2 + ind * c2, 0.f);
                o.w = fmaxf(acc[i][3] + b3 + ind * c3, 0.f);
                *reinterpret_cast<float4*>(out + (size_t)nd * 64 + j0) = o;
            }
        }
    } else {
        float lsum = 0.f;
        float cc[4] = { c0, c1, c2, c3 };
        float bb[4] = { b0, b1, b2, b3 };
        #pragma unroll
        for (int i = 0; i < 8; ++i) {
            int nd = node0 + rowg * 8 + i;
            if (nd < n) {
                float ind = (d_off[nd + 1] > d_off[nd]) ? 1.f : 0.f;
                #pragma unroll
                for (int c = 0; c < 4; ++c) {
                    float x = fmaxf(acc[i][c] + bb[c] + ind * cc[c], 0.f);
                    float t = log1pf(expf(-x));        // x >= 0 so this is stable
                    lsum += (mode == 1) ? t : (x + t);
                }
            }
        }
        int lane = tid & 31, wid = tid >> 5;
        #pragma unroll
        for (int o = 16; o; o >>= 1) lsum += __shfl_down_sync(~0u, lsum, o);
        if (lane == 0) wred[wid] = lsum;
        __syncthreads();
        if (tid < 8) {
            float s = wred[tid];
            #pragma unroll
            for (int o = 4; o; o >>= 1) s += __shfl_down_sync(0xffu, s, o);
            if (tid == 0) atomicAdd(&d_loss, (double)s);
        }
    }
}

__global__ void k_write(float* out, double denom) {
    out[0] = (float)(d_loss / denom);
}

// ---------------- launch ----------------
extern "C" void kernel_launch(void* const* d_in, const int* in_sizes, int n_in,
                              void* d_out, int out_size) {
    const float* nfeats = (const float*)d_in[0];
    const float* efeats = (const float*)d_in[1];
    const int*   src    = (const int*)d_in[2];
    const int*   dst    = (const int*)d_in[3];
    const int*   perm   = (const int*)d_in[4];
    const float* Wm0 = (const float*)d_in[5];
    const float* bm0 = (const float*)d_in[6];
    const float* Wa0 = (const float*)d_in[7];
    const float* ba0 = (const float*)d_in[8];
    const float* Wm1 = (const float*)d_in[9];
    const float* bm1 = (const float*)d_in[10];
    const float* Wa1 = (const float*)d_in[11];
    const float* ba1 = (const float*)d_in[12];

    int n = in_sizes[0] / 64;
    int E = in_sizes[2];
    int nb = (n + 1023) / 1024;

    float *hagg0p, *haggp, *efaggp, *h1p;
    cudaGetSymbolAddress((void**)&hagg0p, d_hagg0);
    cudaGetSymbolAddress((void**)&haggp,  d_hagg);
    cudaGetSymbolAddress((void**)&efaggp, d_efagg);
    cudaGetSymbolAddress((void**)&h1p,    d_h1);

    k_init   <<<(n + 255) / 256, 256>>>(n);
    k_hist   <<<(E + 255) / 256, 256>>>(dst, E);
    k_scan_a <<<nb, 1024>>>(n);
    k_scan_b <<<1, 128>>>(nb, E, n);
    k_scan_c <<<(n + 255) / 256, 256>>>(n);
    k_scatter<<<(E + 255) / 256, 256>>>(src, dst, E);
    k_fold   <<<1, 256>>>(Wm0, bm0, Wa0, 0);
    k_fold   <<<1, 256>>>(Wm1, bm1, Wa1, 1);

    int gw = (n * 32 + 255) / 256;   // one warp per node
    int gl = (n + 127) / 128;        // 128 nodes per GEMM block

    // shared: layer-0 h aggregation of nfeats (same for both views)
    k_agg<<<gw, 256>>>(nfeats, nullptr, 0, hagg0p, n);

    // positive view
    k_agg  <<<gw, 256>>>(efeats, nullptr, 1, efaggp, n);
    k_layer<<<gl, 256>>>(nfeats, hagg0p, efaggp, 0, ba0, h1p, n, 0);
    k_agg  <<<gw, 256>>>(h1p, nullptr, 0, haggp, n);
    k_layer<<<gl, 256>>>(h1p, haggp, efaggp, 1, ba1, nullptr, n, 1);

    // negative view (permuted edge features)
    k_agg  <<<gw, 256>>>(efeats, perm, 1, efaggp, n);
    k_layer<<<gl, 256>>>(nfeats, hagg0p, efaggp, 0, ba0, h1p, n, 0);
    k_agg  <<<gw, 256>>>(h1p, nullptr, 0, haggp, n);
    k_layer<<<gl, 256>>>(h1p, haggp, efaggp, 1, ba1, nullptr, n, 2);

    k_write<<<1, 1>>>((float*)d_out, (double)n * 64.0);
}

// round 2
// speedup vs baseline: 1.2266x; 1.2266x over previous
#include <cuda_runtime.h>
#include <math.h>

#define NN 100000
#define EE 1000000

// ---------------- device scratch ----------------
__device__ int    d_cnt[NN];
__device__ int    d_off[NN + 1];
__device__ int    d_cur[NN];
__device__ int    d_bsum[128];
__device__ int    d_eid[EE];
__device__ int    d_pid[EE];
__device__ int    d_ssrc[EE];
__device__ float  d_hagg0[(size_t)NN * 64];
__device__ float  d_efp [(size_t)NN * 64];
__device__ float  d_efn [(size_t)NN * 64];
__device__ float  d_h1p [(size_t)NN * 64];
__device__ float  d_h1n [(size_t)NN * 64];
__device__ float  d_hp  [(size_t)NN * 64];
__device__ float  d_hn  [(size_t)NN * 64];
__device__ float  d_Wc[2][192 * 64];
__device__ float  d_cv[2][64];
__device__ double d_loss;

// ---------------- f32x2 helpers ----------------
typedef unsigned long long u64;

__device__ __forceinline__ u64 pack2(float x) {
    u64 r; asm("mov.b64 %0,{%1,%1};" : "=l"(r) : "f"(x)); return r;
}
__device__ __forceinline__ void fma2(u64& acc, u64 a, u64 b) {
    asm("fma.rn.f32x2 %0, %1, %2, %0;" : "+l"(acc) : "l"(a), "l"(b));
}
__device__ __forceinline__ float2 unpack2(u64 v) {
    float2 r; asm("mov.b64 {%0,%1},%2;" : "=f"(r.x), "=f"(r.y) : "l"(v)); return r;
}

// ---------------- init / CSR build ----------------
__global__ void k_init(int n) {
    int i = blockIdx.x * blockDim.x + threadIdx.x;
    if (i < n) { d_cnt[i] = 0; d_cur[i] = 0; }
    if (i == 0) d_loss = 0.0;
}

__global__ void k_hist(const int* __restrict__ dst, int E) {
    int e = blockIdx.x * blockDim.x + threadIdx.x;
    if (e < E) atomicAdd(&d_cnt[dst[e]], 1);
}

__global__ void k_scan_a(int n) {
    __shared__ int ws[32];
    int i = blockIdx.x * 1024 + threadIdx.x;
    int lane = threadIdx.x & 31, wid = threadIdx.x >> 5;
    int v = (i < n) ? d_cnt[i] : 0;
    int x = v;
    #pragma unroll
    for (int o = 1; o < 32; o <<= 1) { int y = __shfl_up_sync(~0u, x, o); if (lane >= o) x += y; }
    if (lane == 31) ws[wid] = x;
    __syncthreads();
    if (wid == 0) {
        int w = ws[lane];
        #pragma unroll
        for (int o = 1; o < 32; o <<= 1) { int y = __shfl_up_sync(~0u, w, o); if (lane >= o) w += y; }
        ws[lane] = w;
    }
    __syncthreads();
    int incl = x + (wid > 0 ? ws[wid - 1] : 0);
    if (i < n) d_off[i] = incl - v;
    if (threadIdx.x == 1023) d_bsum[blockIdx.x] = incl;
}

__global__ void k_scan_b(int nb, int Etot, int n) {
    __shared__ int s[128];
    int t = threadIdx.x;
    int orig = (t < nb) ? d_bsum[t] : 0;
    s[t] = orig;
    __syncthreads();
    for (int o = 1; o < 128; o <<= 1) {
        int add = (t >= o) ? s[t - o] : 0;
        __syncthreads();
        s[t] += add;
        __syncthreads();
    }
    if (t < nb) d_bsum[t] = s[t] - orig;
    if (t == 0) d_off[n] = Etot;
}

__global__ void k_scan_c(int n) {
    int i = blockIdx.x * blockDim.x + threadIdx.x;
    if (i < n) d_off[i] += d_bsum[i >> 10];
}

__global__ void k_scatter(const int* __restrict__ src, const int* __restrict__ dst,
                          const int* __restrict__ perm, int E) {
    int e = blockIdx.x * blockDim.x + threadIdx.x;
    if (e < E) {
        int d = dst[e];
        int p = d_off[d] + atomicAdd(&d_cur[d], 1);
        d_eid[p]  = e;
        d_pid[p]  = perm[e];
        d_ssrc[p] = src[e];
    }
}

// ---------------- fold Wmsg into Wapply ----------------
__global__ void k_fold(const float* __restrict__ Wmsg, const float* __restrict__ bmsg,
                       const float* __restrict__ Wap, int layer) {
    __shared__ float Wn[64][64];
    __shared__ float bm[64];
    int tid = threadIdx.x;
    for (int idx = tid; idx < 64 * 64; idx += 256) {
        int j = idx >> 6, t = idx & 63;
        Wn[t][j] = Wap[j * 128 + 64 + t];
    }
    if (tid < 64) bm[tid] = bmsg[tid];
    __syncthreads();
    for (int idx = tid; idx < 192 * 64; idx += 256) {
        int k = idx >> 6, j = idx & 63;
        float r;
        if (k < 64) {
            r = Wap[j * 128 + k];
        } else {
            int col = k - 64;
            float a = 0.f;
            #pragma unroll
            for (int t = 0; t < 64; ++t) a += Wmsg[t * 128 + col] * Wn[t][j];
            r = a;
        }
        d_Wc[layer][k * 64 + j] = r;
    }
    for (int j = tid; j < 64; j += 256) {
        float a = 0.f;
        #pragma unroll
        for (int t = 0; t < 64; ++t) a += bm[t] * Wn[t][j];
        d_cv[layer][j] = a;
    }
}

// ---------------- aggregation kernels ----------------
__global__ void k_aggh(const float* __restrict__ feat, float* __restrict__ out, int n) {
    int gw = (blockIdx.x * blockDim.x + threadIdx.x) >> 5;
    int lane = threadIdx.x & 31;
    if (gw >= n) return;
    int beg = d_off[gw], end = d_off[gw + 1];
    float ax = 0.f, ay = 0.f;
    for (int k = beg; k < end; ++k) {
        int row = __ldg(&d_ssrc[k]);
        float2 v = *reinterpret_cast<const float2*>(feat + (size_t)row * 64 + lane * 2);
        ax += v.x; ay += v.y;
    }
    float inv = 1.f / fmaxf((float)(end - beg), 1.f);
    *reinterpret_cast<float2*>(out + (size_t)gw * 64 + lane * 2) = make_float2(ax * inv, ay * inv);
}

// fused: gather two tables with the same (ssrc) index list
__global__ void k_aggh2(const float* __restrict__ fa, const float* __restrict__ fb,
                        float* __restrict__ oa, float* __restrict__ ob, int n) {
    int gw = (blockIdx.x * blockDim.x + threadIdx.x) >> 5;
    int lane = threadIdx.x & 31;
    if (gw >= n) return;
    int beg = d_off[gw], end = d_off[gw + 1];
    float ax = 0.f, ay = 0.f, bx = 0.f, by = 0.f;
    for (int k = beg; k < end; ++k) {
        int row = __ldg(&d_ssrc[k]);
        float2 va = *reinterpret_cast<const float2*>(fa + (size_t)row * 64 + lane * 2);
        float2 vb = *reinterpret_cast<const float2*>(fb + (size_t)row * 64 + lane * 2);
        ax += va.x; ay += va.y; bx += vb.x; by += vb.y;
    }
    float inv = 1.f / fmaxf((float)(end - beg), 1.f);
    *reinterpret_cast<float2*>(oa + (size_t)gw * 64 + lane * 2) = make_float2(ax * inv, ay * inv);
    *reinterpret_cast<float2*>(ob + (size_t)gw * 64 + lane * 2) = make_float2(bx * inv, by * inv);
}

// fused: ef aggregates for both views (identity eid and permuted pid)
__global__ void k_aggef2(const float* __restrict__ ef,
                         float* __restrict__ op, float* __restrict__ on, int n) {
    int gw = (blockIdx.x * blockDim.x + threadIdx.x) >> 5;
    int lane = threadIdx.x & 31;
    if (gw >= n) return;
    int beg = d_off[gw], end = d_off[gw + 1];
    float px = 0.f, py = 0.f, nx = 0.f, ny = 0.f;
    for (int k = beg; k < end; ++k) {
        int e  = __ldg(&d_eid[k]);
        int pe = __ldg(&d_pid[k]);
        float2 vp = *reinterpret_cast<const float2*>(ef + (size_t)e  * 64 + lane * 2);
        float2 vn = *reinterpret_cast<const float2*>(ef + (size_t)pe * 64 + lane * 2);
        px += vp.x; py += vp.y; nx += vn.x; ny += vn.y;
    }
    float inv = 1.f / fmaxf((float)(end - beg), 1.f);
    *reinterpret_cast<float2*>(op + (size_t)gw * 64 + lane * 2) = make_float2(px * inv, py * inv);
    *reinterpret_cast<float2*>(on + (size_t)gw * 64 + lane * 2) = make_float2(nx * inv, ny * inv);
}

// ---------------- GEMM building blocks (f32x2) ----------------
// Tile: 128 nodes x 64 outputs, 256 threads, each thread: 2 rows x 16 cols.
// Column set of a thread: { colg*4 + m*16 + j : m=0..3, j=0..3 } (conflict-free LDS.128 on W).

__device__ __forceinline__ void stageX(float (*Xs)[66], const float* __restrict__ S,
                                       int node0, int n, int tid) {
    #pragma unroll
    for (int it = 0; it < 8; ++it) {
        int t = tid + it * 256;
        int r = t >> 4;
        int c4 = (t & 15) << 2;
        int nd = node0 + r;
        float4 v = make_float4(0.f, 0.f, 0.f, 0.f);
        if (nd < n) v = *reinterpret_cast<const float4*>(S + (size_t)nd * 64 + c4);
        *reinterpret_cast<float2*>(&Xs[r][c4])     = make_float2(v.x, v.y);
        *reinterpret_cast<float2*>(&Xs[r][c4 + 2]) = make_float2(v.z, v.w);
    }
}

__device__ __forceinline__ void stageW(float (*Ws)[64], const float* __restrict__ Wg, int tid) {
    #pragma unroll
    for (int it = 0; it < 2; ++it) {
        int t = tid + it * 256;
        reinterpret_cast<float4*>(&Ws[0][0])[t] = reinterpret_cast<const float4*>(Wg)[t];
    }
}

__device__ __forceinline__ void panel32(const float (*Xs)[66], const float (*Ws)[64],
                                        u64 acc[2][8], int r0, int cbase) {
    #pragma unroll 8
    for (int k = 0; k < 32; ++k) {
        u64 xx0 = pack2(Xs[r0][k]);
        u64 xx1 = pack2(Xs[r0 + 1][k]);
        #pragma unroll
        for (int m = 0; m < 4; ++m) {
            ulonglong2 w = *reinterpret_cast<const ulonglong2*>(&Ws[k][cbase + (m << 4)]);
            fma2(acc[0][2 * m],     xx0, w.x);
            fma2(acc[0][2 * m + 1], xx0, w.y);
            fma2(acc[1][2 * m],     xx1, w.x);
            fma2(acc[1][2 * m + 1], xx1, w.y);
        }
    }
}

__device__ __forceinline__ void epi_store(u64 acc[2][8], const float* __restrict__ bap,
                                          const float* __restrict__ cv, float* __restrict__ out,
                                          int node0, int r0, int colg, int n) {
    #pragma unroll
    for (int i = 0; i < 2; ++i) {
        int nd = node0 + r0 + i;
        if (nd >= n) break;
        float ind = (d_cnt[nd] > 0) ? 1.f : 0.f;
        #pragma unroll
        for (int m = 0; m < 4; ++m) {
            int c = (colg << 2) + (m << 4);
            float2 a = unpack2(acc[i][2 * m]);
            float2 b = unpack2(acc[i][2 * m + 1]);
            float4 o;
            o.x = fmaxf(a.x + bap[c]     + ind * cv[c],     0.f);
            o.y = fmaxf(a.y + bap[c + 1] + ind * cv[c + 1], 0.f);
            o.z = fmaxf(b.x + bap[c + 2] + ind * cv[c + 2], 0.f);
            o.w = fmaxf(b.y + bap[c + 3] + ind * cv[c + 3], 0.f);
            *reinterpret_cast<float4*>(out + (size_t)nd * 64 + c) = o;
        }
    }
}

// ---------------- layer 0, both views fused (shared base accumulator) ----------------
__global__ void __launch_bounds__(256, 2) k_layer0(
    const float* __restrict__ nfeats, const float* __restrict__ hagg0,
    const float* __restrict__ efp, const float* __restrict__ efn,
    const float* __restrict__ bap, float* __restrict__ outp, float* __restrict__ outn, int n)
{
    __shared__ float Xs[128][66];
    __shared__ float Ws[32][64];
    int tid = threadIdx.x;
    int colg = tid & 3, rowg = tid >> 2;
    int r0 = rowg * 2, cbase = colg << 2;
    int node0 = blockIdx.x * 128;
    const float* Wc = d_Wc[0];

    u64 accB[2][8] = {{0}};

    // shared base: [nfeats, hagg0] @ Wc rows [0,128)
    #pragma unroll
    for (int p = 0; p < 2; ++p) {
        const float* S = p ? hagg0 : nfeats;
        __syncthreads();
        stageX(Xs, S, node0, n, tid);
        #pragma unroll
        for (int h = 0; h < 2; ++h) {
            __syncthreads();
            stageW(Ws, Wc + (p * 64 + h * 32) * 64, tid);
            __syncthreads();
            panel32(Xs, Ws, accB, r0, cbase);
        }
    }

    u64 acc[2][8];

    // positive tail
    #pragma unroll
    for (int i = 0; i < 2; ++i)
        #pragma unroll
        for (int j = 0; j < 8; ++j) acc[i][j] = accB[i][j];
    __syncthreads();
    stageX(Xs, efp, node0, n, tid);
    #pragma unroll
    for (int h = 0; h < 2; ++h) {
        __syncthreads();
        stageW(Ws, Wc + (128 + h * 32) * 64, tid);
        __syncthreads();
        panel32(Xs, Ws, acc, r0, cbase);
    }
    epi_store(acc, bap, d_cv[0], outp, node0, r0, colg, n);

    // negative tail
    #pragma unroll
    for (int i = 0; i < 2; ++i)
        #pragma unroll
        for (int j = 0; j < 8; ++j) acc[i][j] = accB[i][j];
    __syncthreads();
    stageX(Xs, efn, node0, n, tid);
    #pragma unroll
    for (int h = 0; h < 2; ++h) {
        __syncthreads();
        stageW(Ws, Wc + (128 + h * 32) * 64, tid);
        __syncthreads();
        panel32(Xs, Ws, acc, r0, cbase);
    }
    epi_store(acc, bap, d_cv[0], outn, node0, r0, colg, n);
}

// ---------------- layer 1, both views in one launch (blockIdx.y), fused BCE reduce ----------------
__global__ void __launch_bounds__(256, 2) k_layer1(
    const float* __restrict__ h1p, const float* __restrict__ hp, const float* __restrict__ efp,
    const float* __restrict__ h1n, const float* __restrict__ hn, const float* __restrict__ efn,
    const float* __restrict__ bap, int n)
{
    __shared__ float Xs[128][66];
    __shared__ float Ws[32][64];
    __shared__ float wred[8];
    int tid = threadIdx.x;
    int colg = tid & 3, rowg = tid >> 2;
    int r0 = rowg * 2, cbase = colg << 2;
    int node0 = blockIdx.x * 128;
    int view = blockIdx.y;   // 0 = positive (target 1), 1 = negative (target 0)
    const float* Wc = d_Wc[1];

    const float* S0 = view ? h1n : h1p;
    const float* S1 = view ? hn  : hp;
    const float* S2 = view ? efn : efp;

    u64 acc[2][8] = {{0}};

    #pragma unroll
    for (int p = 0; p < 3; ++p) {
        const float* S = (p == 0) ? S0 : (p == 1) ? S1 : S2;
        __syncthreads();
        stageX(Xs, S, node0, n, tid);
        #pragma unroll
        for (int h = 0; h < 2; ++h) {
            __syncthreads();
            stageW(Ws, Wc + (p * 64 + h * 32) * 64, tid);
            __syncthreads();
            panel32(Xs, Ws, acc, r0, cbase);
        }
    }

    // BCE epilogue: x = relu(acc + b + ind*c); pos: log1p(e^-x); neg: x + log1p(e^-x)
    const float* cv = d_cv[1];
    float lsum = 0.f;
    #pragma unroll
    for (int i = 0; i < 2; ++i) {
        int nd = node0 + r0 + i;
        if (nd < n) {
            float ind = (d_cnt[nd] > 0) ? 1.f : 0.f;
            #pragma unroll
            for (int m = 0; m < 4; ++m) {
                int c = (colg << 2) + (m << 4);
                float2 a = unpack2(acc[i][2 * m]);
                float2 b = unpack2(acc[i][2 * m + 1]);
                float xv[4];
                xv[0] = fmaxf(a.x + bap[c]     + ind * cv[c],     0.f);
                xv[1] = fmaxf(a.y + bap[c + 1] + ind * cv[c + 1], 0.f);
                xv[2] = fmaxf(b.x + bap[c + 2] + ind * cv[c + 2], 0.f);
                xv[3] = fmaxf(b.y + bap[c + 3] + ind * cv[c + 3], 0.f);
                #pragma unroll
                for (int j = 0; j < 4; ++j) {
                    float t = log1pf(expf(-xv[j]));
                    lsum += view ? (xv[j] + t) : t;
                }
            }
        }
    }
    int lane = tid & 31, wid = tid >> 5;
    #pragma unroll
    for (int o = 16; o; o >>= 1) lsum += __shfl_down_sync(~0u, lsum, o);
    if (lane == 0) wred[wid] = lsum;
    __syncthreads();
    if (tid < 8) {
        float s = wred[tid];
        #pragma unroll
        for (int o = 4; o; o >>= 1) s += __shfl_down_sync(0xffu, s, o);
        if (tid == 0) atomicAdd(&d_loss, (double)s);
    }
}

__global__ void k_write(float* out, double denom) {
    out[0] = (float)(d_loss / denom);
}

// ---------------- launch ----------------
extern "C" void kernel_launch(void* const* d_in, const int* in_sizes, int n_in,
                              void* d_out, int out_size) {
    const float* nfeats = (const float*)d_in[0];
    const float* efeats = (const float*)d_in[1];
    const int*   src    = (const int*)d_in[2];
    const int*   dst    = (const int*)d_in[3];
    const int*   perm   = (const int*)d_in[4];
    const float* Wm0 = (const float*)d_in[5];
    const float* bm0 = (const float*)d_in[6];
    const float* Wa0 = (const float*)d_in[7];
    const float* ba0 = (const float*)d_in[8];
    const float* Wm1 = (const float*)d_in[9];
    const float* bm1 = (const float*)d_in[10];
    const float* Wa1 = (const float*)d_in[11];
    const float* ba1 = (const float*)d_in[12];

    int n = in_sizes[0] / 64;
    int E = in_sizes[2];
    int nb = (n + 1023) / 1024;

    float *hagg0p, *efpp, *efnp, *h1pp, *h1np, *hpp, *hnp;
    cudaGetSymbolAddress((void**)&hagg0p, d_hagg0);
    cudaGetSymbolAddress((void**)&efpp,   d_efp);
    cudaGetSymbolAddress((void**)&efnp,   d_efn);
    cudaGetSymbolAddress((void**)&h1pp,   d_h1p);
    cudaGetSymbolAddress((void**)&h1np,   d_h1n);
    cudaGetSymbolAddress((void**)&hpp,    d_hp);
    cudaGetSymbolAddress((void**)&hnp,    d_hn);

    k_init   <<<(n + 255) / 256, 256>>>(n);
    k_hist   <<<(E + 255) / 256, 256>>>(dst, E);
    k_scan_a <<<nb, 1024>>>(n);
    k_scan_b <<<1, 128>>>(nb, E, n);
    k_scan_c <<<(n + 255) / 256, 256>>>(n);
    k_scatter<<<(E + 255) / 256, 256>>>(src, dst, perm, E);
    k_fold   <<<1, 256>>>(Wm0, bm0, Wa0, 0);
    k_fold   <<<1, 256>>>(Wm1, bm1, Wa1, 1);

    int gw = (n * 32 + 255) / 256;   // one warp per node
    int gl = (n + 127) / 128;        // 128 nodes per GEMM tile

    k_aggh  <<<gw, 256>>>(nfeats, hagg0p, n);                 // shared across views
    k_aggef2<<<gw, 256>>>(efeats, efpp, efnp, n);             // both ef aggregates
    k_layer0<<<gl, 256>>>(nfeats, hagg0p, efpp, efnp, ba0, h1pp, h1np, n);
    k_aggh2 <<<gw, 256>>>(h1pp, h1np, hpp, hnp, n);           // both h1 aggregates
    {
        dim3 grid(gl, 2);
        k_layer1<<<grid, 256>>>(h1pp, hpp, efpp, h1np, hnp, efnp, ba1, n);
    }
    k_write<<<1, 1>>>((float*)d_out, (double)n * 64.0);
}